// round 4
// baseline (speedup 1.0000x reference)
#include <cuda_runtime.h>
#include <cstdint>

// Cost volume: out[b,k,h,w] = (1/81) * sum_c x1[b,c,h,w] * x2[b,c,h-i,w-j]
//   i,j in [-4,4], k = (9i+j) mod 81. Zero padding. B=4,C=128,H=128,W=256,D=81.
//
// R3: CTA = 288 threads = 9 warps; warp g handles di = g-4 only.
// Tile 4h x 64w; lane covers 8 consecutive w px. acc[9][8] = 72 regs.
// cp.async double-buffered channel chunks of 4. 2 CTAs/SM -> 18 warps.

#define Bn 4
#define Cn 128
#define Hn 128
#define Wn 256
#define Dn 81
#define TH 4
#define TW 64
#define CC 4
#define NCH (Cn / CC)       // 32 chunks
#define S2H (TH + 8)        // 12
#define S2W (TW + 8)        // 72
#define NTHR 288

#define S1_F4 (CC * TH * TW / 4)    // 256
#define S2_F4 (CC * S2H * S2W / 4)  // 864

__device__ __forceinline__ void cp16(uint32_t saddr, const float* gptr, bool ok) {
    int sz = ok ? 16 : 0;
    asm volatile("cp.async.cg.shared.global [%0], [%1], 16, %2;\n"
                 :: "r"(saddr), "l"(gptr), "r"(sz));
}
__device__ __forceinline__ void cp_commit() {
    asm volatile("cp.async.commit_group;\n" ::: "memory");
}
template <int N>
__device__ __forceinline__ void cp_wait() {
    asm volatile("cp.async.wait_group %0;\n" :: "n"(N) : "memory");
}

__global__ __launch_bounds__(NTHR, 2)
void costvol_kernel(const float* __restrict__ x1,
                    const float* __restrict__ x2,
                    float* __restrict__ out) {
    __shared__ __align__(16) float s1[2][CC][TH][TW];   // 2 * 4 KB
    __shared__ __align__(16) float s2[2][CC][S2H][S2W]; // 2 * 13.5 KB

    const int w0 = blockIdx.x * TW;
    const int h0 = blockIdx.y * TH;
    const int b  = blockIdx.z;

    const int tid  = threadIdx.x;
    const int g    = tid >> 5;       // warp id = ii (di = g-4), 0..8
    const int lane = tid & 31;
    const int ty   = lane >> 3;      // 4 rows
    const int txl  = lane & 7;       // 8 lane-columns, 8 px each

    const float* x1b = x1 + (size_t)(b * Cn) * Hn * Wn;
    const float* x2b = x2 + (size_t)(b * Cn) * Hn * Wn;

    auto prefetch = [&](int c0, int st) {
        // s1: 256 float4 (one round, threads 256..287 idle)
        {
            int f = tid;
            if (f < S1_F4) {
                int cc  = f >> 6;                 // 64 f4 per channel
                int rem = f & 63;
                int hh  = rem >> 4;               // 16 f4 per row
                int k4  = rem & 15;
                uint32_t sa = (uint32_t)__cvta_generic_to_shared(&s1[st][cc][hh][4 * k4]);
                cp16(sa, x1b + (((size_t)(c0 + cc) * Hn + h0 + hh) * Wn + w0 + 4 * k4), true);
            }
        }
        // s2: 864 float4 (3 rounds)
#pragma unroll
        for (int q = 0; q < 3; q++) {
            int f = tid + q * NTHR;
            if (f < S2_F4) {
                int cc  = f / (S2H * (S2W / 4));
                int rem = f - cc * (S2H * (S2W / 4));
                int row = rem / (S2W / 4);
                int k4  = rem - row * (S2W / 4);
                int hg  = h0 - 4 + row;
                int wg  = w0 - 4 + 4 * k4;
                bool ok = ((unsigned)hg < (unsigned)Hn) && ((unsigned)wg < (unsigned)Wn);
                const float* gp = ok ? (x2b + (((size_t)cc + c0) * Hn + hg) * (size_t)Wn + wg)
                                     : x2b;
                uint32_t sa = (uint32_t)__cvta_generic_to_shared(&s2[st][cc][row][4 * k4]);
                cp16(sa, gp, ok);
            }
        }
        cp_commit();
    };

    float acc[9][8];
#pragma unroll
    for (int jj = 0; jj < 9; jj++)
#pragma unroll
        for (int p = 0; p < 8; p++) acc[jj][p] = 0.f;

    prefetch(0, 0);

    for (int it = 0; it < NCH; it++) {
        const int st = it & 1;
        if (it + 1 < NCH) {
            prefetch((it + 1) * CC, st ^ 1);
            cp_wait<1>();
        } else {
            cp_wait<0>();
        }
        __syncthreads();

#pragma unroll
        for (int cc = 0; cc < CC; cc++) {
            // a: 8 consecutive x1 px for this lane
            const float4 av0 = *(const float4*)&s1[st][cc][ty][8 * txl];
            const float4 av1 = *(const float4*)&s1[st][cc][ty][8 * txl + 4];
            const float a[8] = {av0.x, av0.y, av0.z, av0.w,
                                av1.x, av1.y, av1.z, av1.w};
            // x2 window: 16 floats starting at w-offset (8*txl - 4), row ty+8-g
            const float* rp = &s2[st][cc][ty + 8 - g][8 * txl];
            float wnd[16];
#pragma unroll
            for (int m = 0; m < 16; m += 4) {
                float4 t = *(const float4*)(rp + m);   // aligned LDS.128
                wnd[m] = t.x; wnd[m + 1] = t.y; wnd[m + 2] = t.z; wnd[m + 3] = t.w;
            }
#pragma unroll
            for (int jj = 0; jj < 9; jj++) {
#pragma unroll
                for (int p = 0; p < 8; p++)
                    acc[jj][p] += a[p] * wnd[p + 8 - jj];
            }
        }
        __syncthreads();
    }

    // ---- epilogue: ii = g, k = (9*g + jj + 41) mod 81 ----
    const float inv = 1.0f / 81.0f;
    const int hg = h0 + ty;
    const int wg = w0 + 8 * txl;
#pragma unroll
    for (int jj = 0; jj < 9; jj++) {
        int k = 9 * g + jj + 41;
        if (k >= 81) k -= 81;
        float* op = out + (((size_t)((b * Dn + k) * Hn + hg)) * Wn + wg);
        float4 v0 = make_float4(acc[jj][0] * inv, acc[jj][1] * inv,
                                acc[jj][2] * inv, acc[jj][3] * inv);
        float4 v1 = make_float4(acc[jj][4] * inv, acc[jj][5] * inv,
                                acc[jj][6] * inv, acc[jj][7] * inv);
        *(float4*)op = v0;
        *(float4*)(op + 4) = v1;
    }
}

extern "C" void kernel_launch(void* const* d_in, const int* in_sizes, int n_in,
                              void* d_out, int out_size) {
    (void)in_sizes; (void)n_in; (void)out_size;
    const float* x1 = (const float*)d_in[0];
    const float* x2 = (const float*)d_in[1];
    float* out = (float*)d_out;
    dim3 grid(Wn / TW, Hn / TH, Bn);   // (4, 32, 4) = 512 blocks
    costvol_kernel<<<grid, NTHR>>>(x1, x2, out);
}

// round 5
// speedup vs baseline: 1.6469x; 1.6469x over previous
#include <cuda_runtime.h>
#include <cstdint>

// Cost volume: out[b,k,h,w] = (1/81) * sum_c x1[b,c,h,w] * x2[b,c,h-i,w-j]
//   i,j in [-4,4], k = (9i+j) mod 81. Zero padding. B=4,C=128,H=128,W=256,D=81.
//
// R4: 288 threads = 9 warps; warp g owns di = g-4. Tile 4h x 32w, P=4 px/lane.
// acc[9][4] = 36 regs -> ~70 live, no spills under launch_bounds(288,2) cap 112.
// cp.async double-buffered CC=4 chunks. 2 CTAs/SM = 18 warps.

#define Bn 4
#define Cn 128
#define Hn 128
#define Wn 256
#define Dn 81
#define TH 4
#define TW 32
#define CC 4
#define NCH (Cn / CC)       // 32 chunks
#define S2H (TH + 8)        // 12
#define S2W (TW + 8)        // 40
#define NTHR 288

#define S1_F4 (CC * TH * TW / 4)    // 128
#define S2_F4 (CC * S2H * S2W / 4)  // 480

__device__ __forceinline__ void cp16(uint32_t saddr, const float* gptr, bool ok) {
    int sz = ok ? 16 : 0;
    asm volatile("cp.async.cg.shared.global [%0], [%1], 16, %2;\n"
                 :: "r"(saddr), "l"(gptr), "r"(sz));
}
__device__ __forceinline__ void cp_commit() {
    asm volatile("cp.async.commit_group;\n" ::: "memory");
}
template <int N>
__device__ __forceinline__ void cp_wait() {
    asm volatile("cp.async.wait_group %0;\n" :: "n"(N) : "memory");
}

__global__ __launch_bounds__(NTHR, 2)
void costvol_kernel(const float* __restrict__ x1,
                    const float* __restrict__ x2,
                    float* __restrict__ out) {
    __shared__ __align__(16) float s1[2][CC][TH][TW];   // 2 * 2 KB
    __shared__ __align__(16) float s2[2][CC][S2H][S2W]; // 2 * 7.5 KB

    const int w0 = blockIdx.x * TW;
    const int h0 = blockIdx.y * TH;
    const int b  = blockIdx.z;

    const int tid  = threadIdx.x;
    const int g    = tid >> 5;       // warp id = ii (di = g-4), 0..8
    const int lane = tid & 31;
    const int ty   = lane >> 3;      // 4 rows
    const int txl  = lane & 7;       // 8 lane-cols * 4 px = 32 w

    const float* x1b = x1 + (size_t)(b * Cn) * Hn * Wn;
    const float* x2b = x2 + (size_t)(b * Cn) * Hn * Wn;

    auto prefetch = [&](int c0, int st) {
        // s1: 128 float4 (threads 0..127)
        if (tid < S1_F4) {
            int cc  = tid >> 5;               // 32 f4 per channel
            int rem = tid & 31;
            int hh  = rem >> 3;               // 8 f4 per row
            int k4  = rem & 7;
            uint32_t sa = (uint32_t)__cvta_generic_to_shared(&s1[st][cc][hh][4 * k4]);
            cp16(sa, x1b + (((size_t)(c0 + cc) * Hn + h0 + hh) * Wn + w0 + 4 * k4), true);
        }
        // s2: 480 float4 (2 rounds of 288)
#pragma unroll
        for (int q = 0; q < 2; q++) {
            int f = tid + q * NTHR;
            if (f < S2_F4) {
                int cc  = f / (S2H * (S2W / 4));
                int rem = f - cc * (S2H * (S2W / 4));
                int row = rem / (S2W / 4);
                int k4  = rem - row * (S2W / 4);
                int hg  = h0 - 4 + row;
                int wg  = w0 - 4 + 4 * k4;
                bool ok = ((unsigned)hg < (unsigned)Hn) && ((unsigned)wg < (unsigned)Wn);
                const float* gp = ok ? (x2b + (((size_t)cc + c0) * Hn + hg) * (size_t)Wn + wg)
                                     : x2b;
                uint32_t sa = (uint32_t)__cvta_generic_to_shared(&s2[st][cc][row][4 * k4]);
                cp16(sa, gp, ok);
            }
        }
        cp_commit();
    };

    float acc[9][4];
#pragma unroll
    for (int jj = 0; jj < 9; jj++)
#pragma unroll
        for (int p = 0; p < 4; p++) acc[jj][p] = 0.f;

    prefetch(0, 0);

    for (int it = 0; it < NCH; it++) {
        const int st = it & 1;
        if (it + 1 < NCH) {
            prefetch((it + 1) * CC, st ^ 1);
            cp_wait<1>();
        } else {
            cp_wait<0>();
        }
        __syncthreads();

#pragma unroll
        for (int cc = 0; cc < CC; cc++) {
            const float4 av = *(const float4*)&s1[st][cc][ty][4 * txl];
            const float a[4] = {av.x, av.y, av.z, av.w};
            // window: 12 floats, row ty+8-g, starting local col 4*txl
            const float* rp = &s2[st][cc][ty + 8 - g][4 * txl];
            float wnd[12];
#pragma unroll
            for (int m = 0; m < 12; m += 4) {
                float4 t = *(const float4*)(rp + m);   // aligned LDS.128
                wnd[m] = t.x; wnd[m + 1] = t.y; wnd[m + 2] = t.z; wnd[m + 3] = t.w;
            }
#pragma unroll
            for (int jj = 0; jj < 9; jj++) {
#pragma unroll
                for (int p = 0; p < 4; p++)
                    acc[jj][p] += a[p] * wnd[p + 8 - jj];
            }
        }
        __syncthreads();
    }

    // ---- epilogue: ii = g, k = (9*g + jj + 41) mod 81 ----
    const float inv = 1.0f / 81.0f;
    const int hg = h0 + ty;
    const int wg = w0 + 4 * txl;
#pragma unroll
    for (int jj = 0; jj < 9; jj++) {
        int k = 9 * g + jj + 41;
        if (k >= 81) k -= 81;
        float4 v = make_float4(acc[jj][0] * inv, acc[jj][1] * inv,
                               acc[jj][2] * inv, acc[jj][3] * inv);
        *(float4*)(out + (((size_t)((b * Dn + k) * Hn + hg)) * Wn + wg)) = v;
    }
}

extern "C" void kernel_launch(void* const* d_in, const int* in_sizes, int n_in,
                              void* d_out, int out_size) {
    (void)in_sizes; (void)n_in; (void)out_size;
    const float* x1 = (const float*)d_in[0];
    const float* x2 = (const float*)d_in[1];
    float* out = (float*)d_out;
    dim3 grid(Wn / TW, Hn / TH, Bn);   // (8, 32, 4) = 1024 blocks
    costvol_kernel<<<grid, NTHR>>>(x1, x2, out);
}